// round 4
// baseline (speedup 1.0000x reference)
#include <cuda_runtime.h>
#include <math.h>

#define N_ROWS 32768
#define IN_DIM 768
#define HID 2048
#define OUT_DIM 256
#define KCODES 1024

// ---------------- scratch (device globals: allocation-free) ----------------
__device__ float g_h[(size_t)N_ROWS * HID];        // 256 MB hidden (enc & dec reuse)
__device__ float g_scores[(size_t)N_ROWS * KCODES];// 128 MB score matrix
__device__ float g_decin[(size_t)N_ROWS * OUT_DIM];// 32 MB zq1+zq2+zq3
__device__ float g_emb2[KCODES];                   // per-code squared norms
__device__ float g_rownorm[N_ROWS];                // per-row ||ze||^2

// ---------------- fp32 SGEMM ----------------
// A: M x K row-major. BTRANS=false: B is K x Ncol row-major (C = act(A@B + bias)).
//                     BTRANS=true:  B is Ncol x K row-major; SCORE epilogue:
//                        C = fl( fl(rowterm[row] + bias[col]) - 2*acc )
// ACT: 0 none, 1 relu, 2 sigmoid.
template<int ACT, bool BTRANS>
__global__ void __launch_bounds__(256) sgemm_kernel(
    const float* __restrict__ A, const float* __restrict__ B,
    const float* __restrict__ bias, const float* __restrict__ rowterm,
    float* __restrict__ C,
    int M, int Ncol, int Kdim)
{
    __shared__ float As[16][128];
    __shared__ float Bs[16][128];

    const int bm = blockIdx.y;
    const int bn = blockIdx.x;
    const int tid = threadIdx.x;
    const int tx = tid & 15;      // 0..15 -> column group
    const int ty = tid >> 4;      // 0..15 -> row group

    const float* Ablk = A + (size_t)bm * 128 * Kdim;

    float acc[8][8];
    #pragma unroll
    for (int i = 0; i < 8; i++)
        #pragma unroll
        for (int j = 0; j < 8; j++) acc[i][j] = 0.0f;

    for (int kt = 0; kt < Kdim; kt += 16) {
        // --- load A tile (128 rows x 16 k), store transposed As[k][row]
        #pragma unroll
        for (int r = 0; r < 2; r++) {
            int L = tid + r * 256;          // 0..511 float4 loads
            int row = L >> 2;
            int k4 = (L & 3) * 4;
            float4 v = *reinterpret_cast<const float4*>(
                Ablk + (size_t)row * Kdim + kt + k4);
            As[k4 + 0][row] = v.x;
            As[k4 + 1][row] = v.y;
            As[k4 + 2][row] = v.z;
            As[k4 + 3][row] = v.w;
        }
        if (!BTRANS) {
            // B[k][m] tile: 16 x 128, coalesced along m
            #pragma unroll
            for (int r = 0; r < 2; r++) {
                int L = tid + r * 256;
                int kk = L >> 5;            // 0..15
                int m4 = (L & 31) * 4;
                float4 v = *reinterpret_cast<const float4*>(
                    B + (size_t)(kt + kk) * Ncol + (size_t)bn * 128 + m4);
                *reinterpret_cast<float4*>(&Bs[kk][m4]) = v;
            }
        } else {
            // B[code][c] tile: 128 codes x 16 c, scatter to Bs[c][code]
            #pragma unroll
            for (int r = 0; r < 2; r++) {
                int L = tid + r * 256;
                int code = L >> 2;
                int c4 = (L & 3) * 4;
                float4 v = *reinterpret_cast<const float4*>(
                    B + (size_t)(bn * 128 + code) * Kdim + kt + c4);
                Bs[c4 + 0][code] = v.x;
                Bs[c4 + 1][code] = v.y;
                Bs[c4 + 2][code] = v.z;
                Bs[c4 + 3][code] = v.w;
            }
        }
        __syncthreads();

        #pragma unroll
        for (int kk = 0; kk < 16; kk++) {
            float4 a0 = *reinterpret_cast<const float4*>(&As[kk][ty * 8]);
            float4 a1 = *reinterpret_cast<const float4*>(&As[kk][ty * 8 + 4]);
            float4 b0 = *reinterpret_cast<const float4*>(&Bs[kk][tx * 8]);
            float4 b1 = *reinterpret_cast<const float4*>(&Bs[kk][tx * 8 + 4]);
            float a[8] = {a0.x, a0.y, a0.z, a0.w, a1.x, a1.y, a1.z, a1.w};
            float b[8] = {b0.x, b0.y, b0.z, b0.w, b1.x, b1.y, b1.z, b1.w};
            #pragma unroll
            for (int i = 0; i < 8; i++)
                #pragma unroll
                for (int j = 0; j < 8; j++)
                    acc[i][j] = fmaf(a[i], b[j], acc[i][j]);
        }
        __syncthreads();
    }

    const int row0 = bm * 128 + ty * 8;
    const int col0 = bn * 128 + tx * 8;
    #pragma unroll
    for (int i = 0; i < 8; i++) {
        float* crow = C + (size_t)(row0 + i) * Ncol + col0;
        float rt = BTRANS ? rowterm[row0 + i] : 0.0f;
        #pragma unroll
        for (int j = 0; j < 8; j++) {
            float v;
            if (BTRANS) {
                // replicate reference rounding: t = fl(s1 + s2); d = fl(t - 2m)
                float t = __fadd_rn(rt, bias[col0 + j]);
                v = __fmaf_rn(-2.0f, acc[i][j], t);
            } else {
                v = acc[i][j] + bias[col0 + j];
                if (ACT == 1) v = fmaxf(v, 0.0f);
                if (ACT == 2) v = 1.0f / (1.0f + expf(-v));
            }
            crow[j] = v;
        }
    }
}

// ---------------- per-code squared norms ----------------
__global__ void __launch_bounds__(256) emb2_kernel(
    const float* __restrict__ emb, float* __restrict__ out)
{
    int warp = (blockIdx.x * 256 + threadIdx.x) >> 5;
    int lane = threadIdx.x & 31;
    if (warp >= KCODES) return;
    const float* e = emb + (size_t)warp * OUT_DIM;
    float s = 0.0f;
    #pragma unroll
    for (int c = lane; c < OUT_DIM; c += 32) s = fmaf(e[c], e[c], s);
    #pragma unroll
    for (int off = 16; off; off >>= 1)
        s += __shfl_down_sync(0xffffffffu, s, off);
    if (lane == 0) out[warp] = s;
}

// ---------------- per-row squared norms (one warp / row) ----------------
__global__ void __launch_bounds__(256) rownorm_kernel(
    const float* __restrict__ z, float* __restrict__ out, int nrows)
{
    int row = (blockIdx.x * 256 + threadIdx.x) >> 5;
    int lane = threadIdx.x & 31;
    if (row >= nrows) return;
    const float* zr = z + (size_t)row * OUT_DIM;
    float s = 0.0f;
    #pragma unroll
    for (int c = lane; c < OUT_DIM; c += 32) s = fmaf(zr[c], zr[c], s);
    #pragma unroll
    for (int off = 16; off; off >>= 1)
        s += __shfl_down_sync(0xffffffffu, s, off);
    if (lane == 0) out[row] = s;
}

// ---------------- argmin over scores + gather zq + residual (+ next rownorm) --
// Tie-break: lowest index (matches jnp.argmin first-occurrence).
__global__ void __launch_bounds__(256) argmin_kernel(
    const float* __restrict__ scores, const float* __restrict__ ze,
    const float* __restrict__ emb,
    float* __restrict__ n_out, float* __restrict__ zq_out,
    float* __restrict__ zenext_out, float* __restrict__ rownorm_out)
{
    int row = (blockIdx.x * 256 + threadIdx.x) >> 5;
    int lane = threadIdx.x & 31;
    if (row >= N_ROWS) return;

    const float* s = scores + (size_t)row * KCODES;
    float best = s[lane];
    int bidx = lane;
    #pragma unroll 8
    for (int i = lane + 32; i < KCODES; i += 32) {
        float v = s[i];
        if (v < best) { best = v; bidx = i; }   // strict < keeps first occurrence
    }
    #pragma unroll
    for (int off = 16; off; off >>= 1) {
        float v2 = __shfl_down_sync(0xffffffffu, best, off);
        int i2 = __shfl_down_sync(0xffffffffu, bidx, off);
        if (v2 < best || (v2 == best && i2 < bidx)) { best = v2; bidx = i2; }
    }
    bidx = __shfl_sync(0xffffffffu, bidx, 0);
    if (lane == 0) n_out[row] = (float)bidx;

    const float* e = emb + (size_t)bidx * OUT_DIM;
    const float* z = ze + (size_t)row * OUT_DIM;
    float* zq = zq_out + (size_t)row * OUT_DIM;
    if (zenext_out) {
        float* zn = zenext_out + (size_t)row * OUT_DIM;
        float nrm = 0.0f;
        #pragma unroll
        for (int c = lane; c < OUT_DIM; c += 32) {
            float ev = e[c];
            float r = z[c] - ev;
            zq[c] = ev;
            zn[c] = r;
            nrm = fmaf(r, r, nrm);
        }
        #pragma unroll
        for (int off = 16; off; off >>= 1)
            nrm += __shfl_down_sync(0xffffffffu, nrm, off);
        if (lane == 0) rownorm_out[row] = nrm;
    } else {
        #pragma unroll
        for (int c = lane; c < OUT_DIM; c += 32) zq[c] = e[c];
    }
}

// ---------------- dec_in = zq1 + zq2 + zq3 ----------------
__global__ void __launch_bounds__(256) add3_kernel(
    const float* __restrict__ a, const float* __restrict__ b,
    const float* __restrict__ c, float* __restrict__ o, int n)
{
    int i = blockIdx.x * 256 + threadIdx.x;
    if (i < n) o[i] = a[i] + b[i] + c[i];
}

// ---------------- launch ----------------
extern "C" void kernel_launch(void* const* d_in, const int* in_sizes, int n_in,
                              void* d_out, int out_size)
{
    const float* x    = (const float*)d_in[0];
    const float* We1  = (const float*)d_in[1];
    const float* be1  = (const float*)d_in[2];
    const float* We2  = (const float*)d_in[3];
    const float* be2  = (const float*)d_in[4];
    const float* Wd1  = (const float*)d_in[5];
    const float* bd1  = (const float*)d_in[6];
    const float* Wd2  = (const float*)d_in[7];
    const float* bd2  = (const float*)d_in[8];
    const float* emb1 = (const float*)d_in[9];
    const float* emb2c= (const float*)d_in[10];
    const float* emb3c= (const float*)d_in[11];

    float* out = (float*)d_out;
    // output layout: recon, ze1, ze2, ze3, zq1, zq2, zq3, n1, n2, n3 (all f32)
    float* recon = out;
    float* ze1 = recon + (size_t)N_ROWS * IN_DIM;
    float* ze2 = ze1 + (size_t)N_ROWS * OUT_DIM;
    float* ze3 = ze2 + (size_t)N_ROWS * OUT_DIM;
    float* zq1 = ze3 + (size_t)N_ROWS * OUT_DIM;
    float* zq2 = zq1 + (size_t)N_ROWS * OUT_DIM;
    float* zq3 = zq2 + (size_t)N_ROWS * OUT_DIM;
    float* n1  = zq3 + (size_t)N_ROWS * OUT_DIM;
    float* n2  = n1 + N_ROWS;
    float* n3  = n2 + N_ROWS;

    float *h, *sc, *decin, *e2, *rn;
    cudaGetSymbolAddress((void**)&h, g_h);
    cudaGetSymbolAddress((void**)&sc, g_scores);
    cudaGetSymbolAddress((void**)&decin, g_decin);
    cudaGetSymbolAddress((void**)&e2, g_emb2);
    cudaGetSymbolAddress((void**)&rn, g_rownorm);

    const dim3 blk(256);

    // ---- encoder ----
    sgemm_kernel<1, false><<<dim3(HID / 128, N_ROWS / 128), blk>>>(
        x, We1, be1, nullptr, h, N_ROWS, HID, IN_DIM);
    sgemm_kernel<0, false><<<dim3(OUT_DIM / 128, N_ROWS / 128), blk>>>(
        h, We2, be2, nullptr, ze1, N_ROWS, OUT_DIM, HID);

    // ---- quantize stage 1 ----
    rownorm_kernel<<<N_ROWS / 8, blk>>>(ze1, rn, N_ROWS);
    emb2_kernel<<<KCODES / 8, blk>>>(emb1, e2);
    sgemm_kernel<0, true><<<dim3(KCODES / 128, N_ROWS / 128), blk>>>(
        ze1, emb1, e2, rn, sc, N_ROWS, KCODES, OUT_DIM);
    argmin_kernel<<<N_ROWS / 8, blk>>>(sc, ze1, emb1, n1, zq1, ze2, rn);

    // ---- quantize stage 2 ----
    emb2_kernel<<<KCODES / 8, blk>>>(emb2c, e2);
    sgemm_kernel<0, true><<<dim3(KCODES / 128, N_ROWS / 128), blk>>>(
        ze2, emb2c, e2, rn, sc, N_ROWS, KCODES, OUT_DIM);
    argmin_kernel<<<N_ROWS / 8, blk>>>(sc, ze2, emb2c, n2, zq2, ze3, rn);

    // ---- quantize stage 3 (residual not an output) ----
    emb2_kernel<<<KCODES / 8, blk>>>(emb3c, e2);
    sgemm_kernel<0, true><<<dim3(KCODES / 128, N_ROWS / 128), blk>>>(
        ze3, emb3c, e2, rn, sc, N_ROWS, KCODES, OUT_DIM);
    argmin_kernel<<<N_ROWS / 8, blk>>>(sc, ze3, emb3c, n3, zq3, nullptr, nullptr);

    // ---- decoder ----
    add3_kernel<<<(N_ROWS * OUT_DIM) / 256, blk>>>(
        zq1, zq2, zq3, decin, N_ROWS * OUT_DIM);
    sgemm_kernel<2, false><<<dim3(HID / 128, N_ROWS / 128), blk>>>(
        decin, Wd1, bd1, nullptr, h, N_ROWS, HID, OUT_DIM);
    sgemm_kernel<0, false><<<dim3(IN_DIM / 128, N_ROWS / 128), blk>>>(
        h, Wd2, bd2, nullptr, recon, N_ROWS, IN_DIM, HID);
}

// round 7
// speedup vs baseline: 1.4723x; 1.4723x over previous
#include <cuda_runtime.h>
#include <cuda_bf16.h>
#include <math.h>
#include <stdint.h>

#define N_ROWS 32768
#define IN_DIM 768
#define HID 2048
#define OUT_DIM 256
#define KCODES 1024

typedef __nv_bfloat16 bf16;

// ---- scratch (device globals) ----
__device__ bf16 g_xs1[(size_t)N_ROWS * IN_DIM], g_xs2[(size_t)N_ROWS * IN_DIM], g_xs3[(size_t)N_ROWS * IN_DIM];
__device__ bf16 g_hs1[(size_t)N_ROWS * HID], g_hs2[(size_t)N_ROWS * HID], g_hs3[(size_t)N_ROWS * HID];
__device__ bf16 g_zs1[(size_t)N_ROWS * OUT_DIM], g_zs2[(size_t)N_ROWS * OUT_DIM], g_zs3[(size_t)N_ROWS * OUT_DIM];
__device__ bf16 g_wt1[(size_t)HID * IN_DIM], g_wt2[(size_t)HID * IN_DIM], g_wt3[(size_t)HID * IN_DIM];
__device__ bf16 g_et1[KCODES * OUT_DIM], g_et2[KCODES * OUT_DIM], g_et3[KCODES * OUT_DIM];
__device__ float g_scores[(size_t)N_ROWS * KCODES];
__device__ float g_emb2[KCODES];
__device__ float g_rownorm[N_ROWS];

// ---- helpers ----
__device__ __forceinline__ uint32_t smem_u32(const void* p) {
    uint32_t a;
    asm("{ .reg .u64 t; cvta.to.shared.u64 t, %1; cvt.u32.u64 %0, t; }" : "=r"(a) : "l"(p));
    return a;
}
__device__ __forceinline__ uint32_t lds32(uint32_t a) {
    uint32_t v; asm volatile("ld.shared.b32 %0, [%1];" : "=r"(v) : "r"(a)); return v;
}
__device__ __forceinline__ void cpasync16(uint32_t s, const void* g) {
    asm volatile("cp.async.cg.shared.global [%0], [%1], 16;" :: "r"(s), "l"(g));
}
__device__ __forceinline__ void mma16816(float* d, const uint32_t* a, const uint32_t* b) {
    asm volatile(
        "mma.sync.aligned.m16n8k16.row.col.f32.bf16.bf16.f32 "
        "{%0,%1,%2,%3}, {%4,%5,%6,%7}, {%8,%9}, {%0,%1,%2,%3};"
        : "+f"(d[0]), "+f"(d[1]), "+f"(d[2]), "+f"(d[3])
        : "r"(a[0]), "r"(a[1]), "r"(a[2]), "r"(a[3]), "r"(b[0]), "r"(b[1]));
}
__device__ __forceinline__ void split3(float v, bf16& b1, bf16& b2, bf16& b3) {
    b1 = __float2bfloat16(v);
    float r = v - __bfloat162float(b1);
    b2 = __float2bfloat16(r);
    b3 = __float2bfloat16(r - __bfloat162float(b2));
}
__device__ __forceinline__ uint32_t pack2(bf16 a, bf16 b) {
    return (uint32_t)__nv_bfloat16_raw(a).x | ((uint32_t)__nv_bfloat16_raw(b).x << 16);
}

// ---- mma.sync emulated-fp32 GEMM ----
// A: MxK bf16 splits (row-major). B: NxK bf16 splits (row-major => B^T).
// Tile 128x128x32, 8 warps (2x4), warp tile 64x32, 3-stage cp.async ring.
// DRAIN: per-16k-step zeroed accumulator, products small->large, FADD drain
// into fp32 sum (kills the HMMA truncation-bias chain).
// EPI: 0 relu->splits, 1 none->fp32+splits, 2 score->fp32, 3 sigmoid->splits, 4 none->fp32
template<int EPI, int NP, bool DRAIN>
__global__ void __launch_bounds__(256, 1) gemmMMA(
    const bf16* __restrict__ A1, const bf16* __restrict__ A2, const bf16* __restrict__ A3,
    const bf16* __restrict__ B1, const bf16* __restrict__ B2, const bf16* __restrict__ B3,
    const float* __restrict__ bias, const float* __restrict__ rowterm,
    float* __restrict__ outF, bf16* __restrict__ O1, bf16* __restrict__ O2, bf16* __restrict__ O3,
    int N, int K)
{
    constexpr int NS = (NP == 6) ? 3 : 2;
    constexpr int TB = 128 * 80;
    constexpr int STG = 2 * NS * TB;
    extern __shared__ char smem[];

    const int tid = threadIdx.x, lane = tid & 31, wid = tid >> 5;
    const int wm = wid >> 2, wn = wid & 3;
    const int m0 = blockIdx.y * 128, n0 = blockIdx.x * 128;
    const uint32_t sbase = smem_u32(smem);
    const int lg = lane >> 2, lk = (lane & 3) * 2;

    const bf16* Asp[3] = {A1, A2, A3};
    const bf16* Bsp[3] = {B1, B2, B3};

    float sum[4][4][4];
    #pragma unroll
    for (int i = 0; i < 4; ++i)
        #pragma unroll
        for (int j = 0; j < 4; ++j)
            #pragma unroll
            for (int q = 0; q < 4; ++q) sum[i][j][q] = 0.0f;

    const int nc = K / 32;

    auto load_chunk = [&](int c) {
        const uint32_t sb = sbase + (c % 3) * STG;
        #pragma unroll
        for (int s = 0; s < NS; ++s) {
            const char* Ag = (const char*)Asp[s] + (size_t)m0 * K * 2 + (size_t)c * 64;
            const char* Bg = (const char*)Bsp[s] + (size_t)n0 * K * 2 + (size_t)c * 64;
            #pragma unroll
            for (int p = 0; p < 2; ++p) {
                int idx = tid + p * 256;
                int r = idx >> 2, seg = idx & 3;
                cpasync16(sb + s * TB + r * 80 + seg * 16, Ag + (size_t)r * K * 2 + seg * 16);
                cpasync16(sb + (NS + s) * TB + r * 80 + seg * 16, Bg + (size_t)r * K * 2 + seg * 16);
            }
        }
    };

    load_chunk(0);
    asm volatile("cp.async.commit_group;" ::: "memory");
    if (1 < nc) load_chunk(1);
    asm volatile("cp.async.commit_group;" ::: "memory");

    // product schedule: group by B split, dominant a1b1 LAST (drain ordering)
    const int bs_seq6[6] = {1, 1, 2, 0, 0, 0}, as_seq6[6] = {0, 1, 0, 1, 2, 0};
    const int bs_seq3[3] = {1, 0, 0},          as_seq3[3] = {0, 1, 0};

    for (int c = 0; c < nc; ++c) {
        if (c + 2 < nc) load_chunk(c + 2);
        asm volatile("cp.async.commit_group;" ::: "memory");
        asm volatile("cp.async.wait_group 2;" ::: "memory");
        __syncthreads();

        const uint32_t sb = sbase + (c % 3) * STG;
        #pragma unroll
        for (int kh = 0; kh < 2; ++kh) {
            uint32_t af[NS][4][4];
            #pragma unroll
            for (int s = 0; s < NS; ++s) {
                const uint32_t Ab = sb + s * TB;
                #pragma unroll
                for (int mf = 0; mf < 4; ++mf) {
                    uint32_t r = Ab + (wm * 64 + mf * 16 + lg) * 80 + (kh * 16 + lk) * 2;
                    af[s][mf][0] = lds32(r);
                    af[s][mf][1] = lds32(r + 8 * 80);
                    af[s][mf][2] = lds32(r + 16);
                    af[s][mf][3] = lds32(r + 8 * 80 + 16);
                }
            }
            float accbuf[4][4][4];
            if (DRAIN) {
                #pragma unroll
                for (int i = 0; i < 4; ++i)
                    #pragma unroll
                    for (int j = 0; j < 4; ++j)
                        #pragma unroll
                        for (int q = 0; q < 4; ++q) accbuf[i][j][q] = 0.0f;
            }
            float (&tgt)[4][4][4] = DRAIN ? accbuf : sum;

            uint32_t bfr[4][2];
            #pragma unroll
            for (int p = 0; p < NP; ++p) {
                const int bs = (NP == 6) ? bs_seq6[p] : bs_seq3[p];
                const int as = (NP == 6) ? as_seq6[p] : as_seq3[p];
                const bool reload = (p == 0) ||
                    ((NP == 6) ? (bs_seq6[p] != bs_seq6[p - 1]) : (bs_seq3[p] != bs_seq3[p - 1]));
                if (reload) {
                    const uint32_t Bb = sb + (NS + bs) * TB;
                    #pragma unroll
                    for (int nf = 0; nf < 4; ++nf) {
                        uint32_t r = Bb + (wn * 32 + nf * 8 + lg) * 80 + (kh * 16 + lk) * 2;
                        bfr[nf][0] = lds32(r);
                        bfr[nf][1] = lds32(r + 16);
                    }
                }
                #pragma unroll
                for (int mf = 0; mf < 4; ++mf)
                    #pragma unroll
                    for (int nf = 0; nf < 4; ++nf)
                        mma16816(tgt[mf][nf], af[as][mf], bfr[nf]);
            }
            if (DRAIN) {
                #pragma unroll
                for (int i = 0; i < 4; ++i)
                    #pragma unroll
                    for (int j = 0; j < 4; ++j)
                        #pragma unroll
                        for (int q = 0; q < 4; ++q)
                            sum[i][j][q] = __fadd_rn(sum[i][j][q], accbuf[i][j][q]);
            }
        }
        __syncthreads();
    }

    // ---- epilogue ----
    #pragma unroll
    for (int mf = 0; mf < 4; ++mf) {
        #pragma unroll
        for (int part = 0; part < 2; ++part) {
            const int row = m0 + wm * 64 + mf * 16 + lg + part * 8;
            const float rt = (EPI == 2) ? __ldg(rowterm + row) : 0.0f;
            #pragma unroll
            for (int nf = 0; nf < 4; ++nf) {
                const int col = n0 + wn * 32 + nf * 8 + lk;
                const float x0 = sum[mf][nf][part * 2 + 0];
                const float x1 = sum[mf][nf][part * 2 + 1];
                if (EPI == 2) {
                    float t0 = __fadd_rn(rt, __ldg(bias + col));
                    float t1 = __fadd_rn(rt, __ldg(bias + col + 1));
                    *(float2*)(outF + (size_t)row * N + col) =
                        make_float2(__fmaf_rn(-2.0f, x0, t0), __fmaf_rn(-2.0f, x1, t1));
                } else {
                    float f0 = x0 + __ldg(bias + col);
                    float f1 = x1 + __ldg(bias + col + 1);
                    if (EPI == 0) { f0 = fmaxf(f0, 0.0f); f1 = fmaxf(f1, 0.0f); }
                    if (EPI == 3) { f0 = 1.0f / (1.0f + expf(-f0)); f1 = 1.0f / (1.0f + expf(-f1)); }
                    if (EPI == 1 || EPI == 4)
                        *(float2*)(outF + (size_t)row * N + col) = make_float2(f0, f1);
                    if (EPI != 4) {
                        bf16 a1, a2, a3, c1, c2, c3;
                        split3(f0, a1, a2, a3);
                        split3(f1, c1, c2, c3);
                        const size_t o = (size_t)row * N + col;
                        *(uint32_t*)(O1 + o) = pack2(a1, c1);
                        *(uint32_t*)(O2 + o) = pack2(a2, c2);
                        *(uint32_t*)(O3 + o) = pack2(a3, c3);
                    }
                }
            }
        }
    }
}

// ---- elementwise split (n4 = n/4) ----
__global__ void __launch_bounds__(256) split_kernel(
    const float* __restrict__ in, bf16* __restrict__ o1, bf16* __restrict__ o2, bf16* __restrict__ o3, int n4)
{
    int i = blockIdx.x * 256 + threadIdx.x;
    if (i >= n4) return;
    float4 v = ((const float4*)in)[i];
    bf16 a1,a2,a3,b1,b2,b3,c1,c2,c3,d1,d2,d3;
    split3(v.x,a1,a2,a3); split3(v.y,b1,b2,b3); split3(v.z,c1,c2,c3); split3(v.w,d1,d2,d3);
    uint2 u;
    u.x = pack2(a1,b1); u.y = pack2(c1,d1); ((uint2*)o1)[i] = u;
    u.x = pack2(a2,b2); u.y = pack2(c2,d2); ((uint2*)o2)[i] = u;
    u.x = pack2(a3,b3); u.y = pack2(c3,d3); ((uint2*)o3)[i] = u;
}

// ---- W[K,N] -> T[N,K] with split ----
__global__ void __launch_bounds__(256) wsplit_kernel(
    const float* __restrict__ W, bf16* __restrict__ T1, bf16* __restrict__ T2, bf16* __restrict__ T3,
    int K, int N)
{
    __shared__ float t[32][33];
    int tx = threadIdx.x & 31, ty = threadIdx.x >> 5;
    int kb = blockIdx.y * 32, nb = blockIdx.x * 32;
    #pragma unroll
    for (int i = 0; i < 4; ++i)
        t[ty + 8*i][tx] = W[(size_t)(kb + ty + 8*i) * N + nb + tx];
    __syncthreads();
    #pragma unroll
    for (int i = 0; i < 4; ++i) {
        float v = t[tx][ty + 8*i];
        size_t o = (size_t)(nb + ty + 8*i) * K + kb + tx;
        bf16 b1,b2,b3; split3(v,b1,b2,b3);
        T1[o]=b1; T2[o]=b2; T3[o]=b3;
    }
}

__global__ void __launch_bounds__(256) emb2_kernel(const float* __restrict__ emb, float* __restrict__ out)
{
    int warp = (blockIdx.x * 256 + threadIdx.x) >> 5, lane = threadIdx.x & 31;
    if (warp >= KCODES) return;
    const float* e = emb + (size_t)warp * OUT_DIM;
    float s = 0.0f;
    for (int c = lane; c < OUT_DIM; c += 32) s = fmaf(e[c], e[c], s);
    for (int off = 16; off; off >>= 1) s += __shfl_down_sync(0xffffffffu, s, off);
    if (lane == 0) out[warp] = s;
}

__global__ void __launch_bounds__(256) rownorm_kernel(const float* __restrict__ z, float* __restrict__ out)
{
    int row = (blockIdx.x * 256 + threadIdx.x) >> 5, lane = threadIdx.x & 31;
    if (row >= N_ROWS) return;
    const float* zr = z + (size_t)row * OUT_DIM;
    float s = 0.0f;
    for (int c = lane; c < OUT_DIM; c += 32) s = fmaf(zr[c], zr[c], s);
    for (int off = 16; off; off >>= 1) s += __shfl_down_sync(0xffffffffu, s, off);
    if (lane == 0) out[row] = s;
}

// ---- argmin + gather + residual (+ splits + next rownorm) ----
__global__ void __launch_bounds__(256) argmin_kernel(
    const float* __restrict__ scores, const float* __restrict__ ze, const float* __restrict__ emb,
    float* __restrict__ n_out, float* __restrict__ zq_out, float* __restrict__ zenext_out,
    float* __restrict__ rownorm_out, bf16* __restrict__ Z1, bf16* __restrict__ Z2, bf16* __restrict__ Z3)
{
    int row = (blockIdx.x * 256 + threadIdx.x) >> 5, lane = threadIdx.x & 31;
    if (row >= N_ROWS) return;
    const float* s = scores + (size_t)row * KCODES;
    float best = s[lane];
    int bidx = lane;
    #pragma unroll 8
    for (int i = lane + 32; i < KCODES; i += 32) {
        float v = s[i];
        if (v < best) { best = v; bidx = i; }
    }
    #pragma unroll
    for (int off = 16; off; off >>= 1) {
        float v2 = __shfl_down_sync(0xffffffffu, best, off);
        int i2 = __shfl_down_sync(0xffffffffu, bidx, off);
        if (v2 < best || (v2 == best && i2 < bidx)) { best = v2; bidx = i2; }
    }
    bidx = __shfl_sync(0xffffffffu, bidx, 0);
    if (lane == 0) n_out[row] = (float)bidx;

    const float* e = emb + (size_t)bidx * OUT_DIM;
    const float* z = ze + (size_t)row * OUT_DIM;
    float* zq = zq_out + (size_t)row * OUT_DIM;
    if (zenext_out) {
        float* zn = zenext_out + (size_t)row * OUT_DIM;
        size_t ob = (size_t)row * OUT_DIM;
        float nrm = 0.0f;
        for (int c = lane; c < OUT_DIM; c += 32) {
            float ev = e[c], r = z[c] - ev;
            zq[c] = ev; zn[c] = r;
            bf16 b1,b2,b3; split3(r,b1,b2,b3);
            Z1[ob+c]=b1; Z2[ob+c]=b2; Z3[ob+c]=b3;
            nrm = fmaf(r, r, nrm);
        }
        for (int off = 16; off; off >>= 1) nrm += __shfl_down_sync(0xffffffffu, nrm, off);
        if (lane == 0) rownorm_out[row] = nrm;
    } else {
        for (int c = lane; c < OUT_DIM; c += 32) zq[c] = e[c];
    }
}

__global__ void __launch_bounds__(256) add3split_kernel(
    const float* __restrict__ a, const float* __restrict__ b, const float* __restrict__ c,
    bf16* __restrict__ o1, bf16* __restrict__ o2, bf16* __restrict__ o3, int n)
{
    int i = blockIdx.x * 256 + threadIdx.x;
    if (i >= n) return;
    float v = a[i] + b[i] + c[i];
    bf16 b1,b2,b3; split3(v,b1,b2,b3);
    o1[i]=b1; o2[i]=b2; o3[i]=b3;
}

// ---- launch ----
extern "C" void kernel_launch(void* const* d_in, const int* in_sizes, int n_in,
                              void* d_out, int out_size)
{
    const float* x    = (const float*)d_in[0];
    const float* We1  = (const float*)d_in[1];
    const float* be1  = (const float*)d_in[2];
    const float* We2  = (const float*)d_in[3];
    const float* be2  = (const float*)d_in[4];
    const float* Wd1  = (const float*)d_in[5];
    const float* bd1  = (const float*)d_in[6];
    const float* Wd2  = (const float*)d_in[7];
    const float* bd2  = (const float*)d_in[8];
    const float* emb1 = (const float*)d_in[9];
    const float* emb2c= (const float*)d_in[10];
    const float* emb3c= (const float*)d_in[11];

    float* out = (float*)d_out;
    float* recon = out;
    float* ze1 = recon + (size_t)N_ROWS * IN_DIM;
    float* ze2 = ze1 + (size_t)N_ROWS * OUT_DIM;
    float* ze3 = ze2 + (size_t)N_ROWS * OUT_DIM;
    float* zq1 = ze3 + (size_t)N_ROWS * OUT_DIM;
    float* zq2 = zq1 + (size_t)N_ROWS * OUT_DIM;
    float* zq3 = zq2 + (size_t)N_ROWS * OUT_DIM;
    float* n1  = zq3 + (size_t)N_ROWS * OUT_DIM;
    float* n2  = n1 + N_ROWS;
    float* n3  = n2 + N_ROWS;

    bf16 *xs1,*xs2,*xs3,*hs1,*hs2,*hs3,*zs1,*zs2,*zs3,*wt1,*wt2,*wt3,*et1,*et2,*et3;
    float *sc,*e2,*rn;
    cudaGetSymbolAddress((void**)&xs1, g_xs1); cudaGetSymbolAddress((void**)&xs2, g_xs2);
    cudaGetSymbolAddress((void**)&xs3, g_xs3); cudaGetSymbolAddress((void**)&hs1, g_hs1);
    cudaGetSymbolAddress((void**)&hs2, g_hs2); cudaGetSymbolAddress((void**)&hs3, g_hs3);
    cudaGetSymbolAddress((void**)&zs1, g_zs1); cudaGetSymbolAddress((void**)&zs2, g_zs2);
    cudaGetSymbolAddress((void**)&zs3, g_zs3); cudaGetSymbolAddress((void**)&wt1, g_wt1);
    cudaGetSymbolAddress((void**)&wt2, g_wt2); cudaGetSymbolAddress((void**)&wt3, g_wt3);
    cudaGetSymbolAddress((void**)&et1, g_et1); cudaGetSymbolAddress((void**)&et2, g_et2);
    cudaGetSymbolAddress((void**)&et3, g_et3); cudaGetSymbolAddress((void**)&sc, g_scores);
    cudaGetSymbolAddress((void**)&e2, g_emb2); cudaGetSymbolAddress((void**)&rn, g_rownorm);

    const int SMEM6 = 3 * (2 * 3 * 128 * 80);   // 184320
    const int SMEM3 = 3 * (2 * 2 * 128 * 80);   // 122880
    cudaFuncSetAttribute(gemmMMA<0,6,true>,  cudaFuncAttributeMaxDynamicSharedMemorySize, SMEM6);
    cudaFuncSetAttribute(gemmMMA<1,6,true>,  cudaFuncAttributeMaxDynamicSharedMemorySize, SMEM6);
    cudaFuncSetAttribute(gemmMMA<2,6,true>,  cudaFuncAttributeMaxDynamicSharedMemorySize, SMEM6);
    cudaFuncSetAttribute(gemmMMA<3,3,false>, cudaFuncAttributeMaxDynamicSharedMemorySize, SMEM3);
    cudaFuncSetAttribute(gemmMMA<4,3,false>, cudaFuncAttributeMaxDynamicSharedMemorySize, SMEM3);

    const dim3 blk(256);
    const int MTILES = N_ROWS / 128;

    // encoder
    split_kernel<<<(N_ROWS * IN_DIM / 4 + 255) / 256, blk>>>(x, xs1, xs2, xs3, N_ROWS * IN_DIM / 4);
    wsplit_kernel<<<dim3(HID / 32, IN_DIM / 32), blk>>>(We1, wt1, wt2, wt3, IN_DIM, HID);
    gemmMMA<0,6,true><<<dim3(HID / 128, MTILES), blk, SMEM6>>>(
        xs1, xs2, xs3, wt1, wt2, wt3, be1, nullptr, nullptr, hs1, hs2, hs3, HID, IN_DIM);
    wsplit_kernel<<<dim3(OUT_DIM / 32, HID / 32), blk>>>(We2, wt1, wt2, wt3, HID, OUT_DIM);
    gemmMMA<1,6,true><<<dim3(OUT_DIM / 128, MTILES), blk, SMEM6>>>(
        hs1, hs2, hs3, wt1, wt2, wt3, be2, nullptr, ze1, zs1, zs2, zs3, OUT_DIM, HID);

    // stage 1
    rownorm_kernel<<<N_ROWS / 8, blk>>>(ze1, rn);
    split_kernel<<<(KCODES * OUT_DIM / 4 + 255) / 256, blk>>>(emb1, et1, et2, et3, KCODES * OUT_DIM / 4);
    emb2_kernel<<<KCODES / 8, blk>>>(emb1, e2);
    gemmMMA<2,6,true><<<dim3(KCODES / 128, MTILES), blk, SMEM6>>>(
        zs1, zs2, zs3, et1, et2, et3, e2, rn, sc, nullptr, nullptr, nullptr, KCODES, OUT_DIM);
    argmin_kernel<<<N_ROWS / 8, blk>>>(sc, ze1, emb1, n1, zq1, ze2, rn, zs1, zs2, zs3);

    // stage 2
    split_kernel<<<(KCODES * OUT_DIM / 4 + 255) / 256, blk>>>(emb2c, et1, et2, et3, KCODES * OUT_DIM / 4);
    emb2_kernel<<<KCODES / 8, blk>>>(emb2c, e2);
    gemmMMA<2,6,true><<<dim3(KCODES / 128, MTILES), blk, SMEM6>>>(
        zs1, zs2, zs3, et1, et2, et3, e2, rn, sc, nullptr, nullptr, nullptr, KCODES, OUT_DIM);
    argmin_kernel<<<N_ROWS / 8, blk>>>(sc, ze2, emb2c, n2, zq2, ze3, rn, zs1, zs2, zs3);

    // stage 3
    split_kernel<<<(KCODES * OUT_DIM / 4 + 255) / 256, blk>>>(emb3c, et1, et2, et3, KCODES * OUT_DIM / 4);
    emb2_kernel<<<KCODES / 8, blk>>>(emb3c, e2);
    gemmMMA<2,6,true><<<dim3(KCODES / 128, MTILES), blk, SMEM6>>>(
        zs1, zs2, zs3, et1, et2, et3, e2, rn, sc, nullptr, nullptr, nullptr, KCODES, OUT_DIM);
    argmin_kernel<<<N_ROWS / 8, blk>>>(sc, ze3, emb3c, n3, zq3, nullptr, nullptr, nullptr, nullptr, nullptr);

    // decoder
    add3split_kernel<<<(N_ROWS * OUT_DIM + 255) / 256, blk>>>(
        zq1, zq2, zq3, zs1, zs2, zs3, N_ROWS * OUT_DIM);
    wsplit_kernel<<<dim3(HID / 32, OUT_DIM / 32), blk>>>(Wd1, wt1, wt2, wt3, OUT_DIM, HID);
    gemmMMA<3,3,false><<<dim3(HID / 128, MTILES), blk, SMEM3>>>(
        zs1, zs2, zs3, wt1, wt2, wt3, bd1, nullptr, nullptr, hs1, hs2, hs3, HID, OUT_DIM);
    wsplit_kernel<<<dim3(IN_DIM / 32, HID / 32), blk>>>(Wd2, wt1, wt2, wt3, HID, IN_DIM);
    gemmMMA<4,3,false><<<dim3(IN_DIM / 128, MTILES), blk, SMEM3>>>(
        hs1, hs2, hs3, wt1, wt2, wt3, bd2, nullptr, recon, nullptr, nullptr, nullptr, IN_DIM, HID);
}